// round 16
// baseline (speedup 1.0000x reference)
#include <cuda_runtime.h>
#include <math.h>

#define HH 64
#define WW 64
#define NUM_POS 48
#define CC 384
#define BB 32
#define PLANES_PER_CTA 8

struct __align__(16) PosParam {
    float wx0, wx1, wx2;
    float wy0, wy1, wy2;
    int   ox, oy;
};

__device__ PosParam g_pp[NUM_POS];

// ---- tiny LUT kernel: separable normalized Gaussian weights per position ----
__global__ void precompute_weights(const float* __restrict__ offset)
{
    const int p = threadIdx.x;
    if (p >= NUM_POS) return;
    const float offx = offset[p * 2 + 0];
    const float offy = offset[p * 2 + 1];
    const float rx = rintf(offx);                 // == iw*16 exactly (jitter < 0.5)
    const float ry = rintf(offy);
    const float fx = offx - rx;
    const float fy = offy - ry;

    float gx[3], gy[3], sx = 0.f, sy = 0.f;
    #pragma unroll
    for (int k = 0; k < 3; k++) {
        const float dx = (float)(k - 1) + fx;
        const float dy = (float)(k - 1) + fy;
        gx[k] = expf(-2.0f * dx * dx);            // sigma = 0.5
        gy[k] = expf(-2.0f * dy * dy);
        sx += gx[k];
        sy += gy[k];
    }
    const float ix = 1.0f / sx, iy = 1.0f / sy;   // normalizer factors (separable)
    PosParam pp;
    pp.wx0 = gx[0] * ix; pp.wx1 = gx[1] * ix; pp.wx2 = gx[2] * ix;
    pp.wy0 = gy[0] * iy; pp.wy1 = gy[1] * iy; pp.wy2 = gy[2] * iy;
    pp.ox = (int)rx;     pp.oy = (int)ry;
    g_pp[p] = pp;
}

// ---- main fused kernel: displace + separable 3x3 Gaussian, no smem ----
// Each thread: one 4-col x 64-row column strip, rolling the 3-row hconv
// window down the plane -> every source element loaded exactly once.
// 128 threads = 8 planes/CTA (16 threads per plane); all 8 planes share
// one pos (CC % 8 == 0) -> uniform params & predicates per CTA.
__global__ __launch_bounds__(128, 12)
void displace_gauss_kernel(const float* __restrict__ inp,
                           float* __restrict__ out)
{
    const int tid   = threadIdx.x;
    const int plane = blockIdx.x * PLANES_PER_CTA + (tid >> 4);
    const int cg    = tid & 15;
    const int x4    = cg << 2;

    // uniform per CTA: all its planes map to the same position
    const int pos = ((blockIdx.x * PLANES_PER_CTA) % CC) >> 3;
    const PosParam pp = g_pp[pos];
    const int ox = pp.ox, oy = pp.oy;   // multiples of 16 by construction
    const float wx0 = pp.wx0, wx1 = pp.wx1, wx2 = pp.wx2;
    const float wy0 = pp.wy0, wy1 = pp.wy1, wy2 = pp.wy2;

    const int sx = x4 - ox;             // source col of displaced col x4 (mult of 4)
    const bool okm = (unsigned)sx <= 60u;                      // main float4 valid
    const bool okl = (cg > 0)  && ((unsigned)(sx - 4) <= 60u); // col x4-1 valid
    const bool okr = (cg < 15) && ((unsigned)(sx + 4) <= 60u); // col x4+4 valid

    const float* __restrict__ src = inp + (size_t)plane * (HH * WW);
    float* __restrict__ dst       = out + (size_t)plane * (HH * WW);

    // hconv of displaced row at source pointer p (predicated loads)
    #define HLOAD(H, P, ROK)                                                   \
        {                                                                      \
            float4 v = make_float4(0.f, 0.f, 0.f, 0.f);                        \
            float lf = 0.f, rt = 0.f;                                          \
            if ((ROK) & okm) v  = *(const float4*)((P) + sx);                  \
            if ((ROK) & okl) lf = (P)[sx - 1];                                 \
            if ((ROK) & okr) rt = (P)[sx + 4];                                 \
            H.x = fmaf(wx0, lf,  fmaf(wx1, v.x, wx2 * v.y));                   \
            H.y = fmaf(wx0, v.x, fmaf(wx1, v.y, wx2 * v.z));                   \
            H.z = fmaf(wx0, v.y, fmaf(wx1, v.z, wx2 * v.w));                   \
            H.w = fmaf(wx0, v.z, fmaf(wx1, v.w, wx2 * rt));                    \
        }

    float4 h0, h1, h2;
    h1 = make_float4(0.f, 0.f, 0.f, 0.f);        // hconv(displaced row -1) = 0

    // displaced row 0
    {
        const bool rok0 = (unsigned)(0 - oy) < (unsigned)HH;
        const float* p0 = src + (0 - oy) * WW;
        HLOAD(h2, p0, rok0);
    }

    const float* p = src + (1 - oy) * WW;        // source ptr for displaced row 1
    float*       d = dst;                        // output row 0

    #pragma unroll 4
    for (int y = 1; y <= 64; y++) {
        h0 = h1;
        h1 = h2;
        const bool rok = ((unsigned)(y - oy) < (unsigned)HH) & (y < HH);
        HLOAD(h2, p, rok);                       // y==64 -> rok false -> zeros

        float4 o;                                // output row y-1
        o.x = fmaf(wy0, h0.x, fmaf(wy1, h1.x, wy2 * h2.x));
        o.y = fmaf(wy0, h0.y, fmaf(wy1, h1.y, wy2 * h2.y));
        o.z = fmaf(wy0, h0.z, fmaf(wy1, h1.z, wy2 * h2.z));
        o.w = fmaf(wy0, h0.w, fmaf(wy1, h1.w, wy2 * h2.w));
        *(float4*)(d + x4) = o;

        p += WW;
        d += WW;
    }
    #undef HLOAD
}

extern "C" void kernel_launch(void* const* d_in, const int* in_sizes, int n_in,
                              void* d_out, int out_size)
{
    const float* inp    = (const float*)d_in[0];   // (32, 384, 64, 64) fp32
    const float* offset = (const float*)d_in[1];   // (48, 2) fp32
    float* out          = (float*)d_out;           // (32, 384, 64, 64) fp32

    precompute_weights<<<1, 64>>>(offset);
    const int nplanes = BB * CC;                   // 12288
    displace_gauss_kernel<<<nplanes / PLANES_PER_CTA, 128>>>(inp, out);
}

// round 17
// speedup vs baseline: 1.5003x; 1.5003x over previous
#include <cuda_runtime.h>
#include <math.h>

#define HH 64
#define WW 64
#define NUM_POS 48
#define CC 384
#define BB 32

struct __align__(16) PosParam {
    float wx0, wx1, wx2;
    float wy0, wy1, wy2;
    int   ox, oy;
};

__device__ PosParam g_pp[NUM_POS];

// ---- tiny LUT kernel: separable normalized Gaussian weights per position ----
__global__ void precompute_weights(const float* __restrict__ offset)
{
    const int p = threadIdx.x;
    if (p >= NUM_POS) return;
    const float offx = offset[p * 2 + 0];
    const float offy = offset[p * 2 + 1];
    const float rx = rintf(offx);                 // == iw*16 exactly (jitter < 0.5)
    const float ry = rintf(offy);
    const float fx = offx - rx;
    const float fy = offy - ry;

    float gx[3], gy[3], sx = 0.f, sy = 0.f;
    #pragma unroll
    for (int k = 0; k < 3; k++) {
        const float dx = (float)(k - 1) + fx;
        const float dy = (float)(k - 1) + fy;
        gx[k] = expf(-2.0f * dx * dx);            // sigma = 0.5
        gy[k] = expf(-2.0f * dy * dy);
        sx += gx[k];
        sy += gy[k];
    }
    const float ix = 1.0f / sx, iy = 1.0f / sy;   // normalizer factors (separable)
    PosParam pp;
    pp.wx0 = gx[0] * ix; pp.wx1 = gx[1] * ix; pp.wx2 = gx[2] * ix;
    pp.wy0 = gy[0] * iy; pp.wy1 = gy[1] * iy; pp.wy2 = gy[2] * iy;
    pp.ox = (int)rx;     pp.oy = (int)ry;
    g_pp[p] = pp;
}

// ---- main fused kernel: displace + separable 3x3 Gaussian, no smem ----
// One plane per CTA (128 threads): 16 column-groups x 8 row-strips,
// each thread produces a 4-col x 8-row patch reading 10 displaced rows
// directly from global (fully unrolled -> independent LDGs, high MLP).
__global__ __launch_bounds__(128, 12)
void displace_gauss_kernel(const float* __restrict__ inp,
                           float* __restrict__ out)
{
    const int tid   = threadIdx.x;
    const int plane = blockIdx.x;
    const int cg    = tid & 15;          // column group: cols x4..x4+3
    const int strip = tid >> 4;          // row strip: rows y0..y0+7
    const int x4 = cg << 2;
    const int y0 = strip << 3;

    const PosParam pp = g_pp[(plane % CC) >> 3];
    const int ox = pp.ox, oy = pp.oy;    // multiples of 16 by construction
    const float wx0 = pp.wx0, wx1 = pp.wx1, wx2 = pp.wx2;
    const float wy0 = pp.wy0, wy1 = pp.wy1, wy2 = pp.wy2;

    const int sx = x4 - ox;              // source col of displaced col x4 (mult of 4)
    const bool okm = (unsigned)sx <= 60u;                      // main float4 valid
    const bool okl = (cg > 0)  && ((unsigned)(sx - 4) <= 60u); // col x4-1 valid
    const bool okr = (cg < 15) && ((unsigned)(sx + 4) <= 60u); // col x4+4 valid

    const float* __restrict__ src = inp + (size_t)plane * (HH * WW);
    float* __restrict__ dst       = out + (size_t)plane * (HH * WW);

    #define HLOAD(H, ROWY)                                                     \
        {                                                                      \
            const int _y  = (ROWY);                                            \
            const int _sy = _y - oy;                                           \
            const bool _rok = ((unsigned)_y < (unsigned)HH) &                  \
                              ((unsigned)_sy < (unsigned)HH);                  \
            const float* _p = src + _sy * WW;                                  \
            float4 v = make_float4(0.f, 0.f, 0.f, 0.f);                        \
            float lf = 0.f, rt = 0.f;                                          \
            if (_rok & okm) v  = *(const float4*)(_p + sx);                    \
            if (_rok & okl) lf = _p[sx - 1];                                   \
            if (_rok & okr) rt = _p[sx + 4];                                   \
            H.x = fmaf(wx0, lf,  fmaf(wx1, v.x, wx2 * v.y));                   \
            H.y = fmaf(wx0, v.x, fmaf(wx1, v.y, wx2 * v.z));                   \
            H.z = fmaf(wx0, v.y, fmaf(wx1, v.z, wx2 * v.w));                   \
            H.w = fmaf(wx0, v.z, fmaf(wx1, v.w, wx2 * rt));                    \
        }

    float4 h0, h1, h2;
    HLOAD(h1, y0 - 1);                   // displaced row y0-1 (zeros if OOB)
    HLOAD(h2, y0);                       // displaced row y0

    #pragma unroll
    for (int r = 0; r < 8; r++) {
        h0 = h1;
        h1 = h2;
        HLOAD(h2, y0 + 1 + r);           // displaced row y0+r+1

        float4 o;                        // output row y0+r
        o.x = fmaf(wy0, h0.x, fmaf(wy1, h1.x, wy2 * h2.x));
        o.y = fmaf(wy0, h0.y, fmaf(wy1, h1.y, wy2 * h2.y));
        o.z = fmaf(wy0, h0.z, fmaf(wy1, h1.z, wy2 * h2.z));
        o.w = fmaf(wy0, h0.w, fmaf(wy1, h1.w, wy2 * h2.w));
        *(float4*)&dst[(y0 + r) * WW + x4] = o;
    }
    #undef HLOAD
}

extern "C" void kernel_launch(void* const* d_in, const int* in_sizes, int n_in,
                              void* d_out, int out_size)
{
    const float* inp    = (const float*)d_in[0];   // (32, 384, 64, 64) fp32
    const float* offset = (const float*)d_in[1];   // (48, 2) fp32
    float* out          = (float*)d_out;           // (32, 384, 64, 64) fp32

    precompute_weights<<<1, 64>>>(offset);
    displace_gauss_kernel<<<BB * CC, 128>>>(inp, out);
}